// round 3
// baseline (speedup 1.0000x reference)
#include <cuda_runtime.h>

#define DIM   128
#define LMAX  20
#define EPW   4      // elements per warp
#define WPB   8      // warps per block  -> 32 elements per CTA

__device__ float g_partials[2048];

__global__ void __launch_bounds__(256) sg_loss_kernel(
    const float* __restrict__ W0,
    const float* __restrict__ W1,
    const int* __restrict__ target,
    const int* __restrict__ context,
    const int* __restrict__ codes,
    const int* __restrict__ lengths,
    int B, int n_nodes)
{
    const int lane  = threadIdx.x & 31;
    const int wid   = threadIdx.x >> 5;
    const int gwarp = blockIdx.x * WPB + wid;
    const int base  = gwarp * EPW;

    float acc = 0.0f;   // per-lane accumulator over all 4 elements

    if (base < B) {
        // ---- phase 1: issue ALL independent loads up front ----
        int t[EPW], c[EPW], len[EPW], code[EPW];
        #pragma unroll
        for (int e = 0; e < EPW; ++e) {
            const int i = base + e;
            t[e]   = (i < B) ? target[i]  : 0;   // broadcast loads
            c[e]   = (i < B) ? context[i] : 0;
            len[e] = (i < B) ? lengths[i] : 0;
            code[e] = (i < B && lane < LMAX) ? codes[i * LMAX + lane] : 0;
        }

        // ---- phase 2: 8 row gathers back-to-back (MLP=8) ----
        float4 a[EPW], b[EPW];
        #pragma unroll
        for (int e = 0; e < EPW; ++e) {
            const bool ok = (base + e < B) &&
                            t[e] >= 0 && t[e] < n_nodes &&
                            c[e] >= 0 && c[e] < n_nodes;
            const long long ti = ok ? (long long)t[e] : 0;
            const long long ci = ok ? (long long)c[e] : 0;
            a[e] = reinterpret_cast<const float4*>(W0 + ti * DIM)[lane];
            b[e] = reinterpret_cast<const float4*>(W1 + ci * DIM)[lane];
            if (!ok) len[e] = 0;   // contributes nothing
        }

        // ---- phase 3: compute ----
        #pragma unroll
        for (int e = 0; e < EPW; ++e) {
            float dot = a[e].x * b[e].x + a[e].y * b[e].y
                      + a[e].z * b[e].z + a[e].w * b[e].w;
            #pragma unroll
            for (int o = 16; o > 0; o >>= 1)
                dot += __shfl_xor_sync(0xffffffffu, dot, o);
            // all lanes hold full dot; lanes 0..len-1 evaluate tree levels
            if (lane < len[e]) {
                const float sign = 1.0f - 2.0f * (float)code[e];
                const float x = sign * dot;
                // stable log_sigmoid: min(x,0) - log1p(exp(-|x|))
                acc -= fminf(x, 0.0f) - log1pf(__expf(-fabsf(x)));
            }
        }
    }

    // warp reduce acc
    #pragma unroll
    for (int o = 16; o > 0; o >>= 1)
        acc += __shfl_xor_sync(0xffffffffu, acc, o);

    // block reduce: one partial per warp, no atomics
    __shared__ float smem[WPB];
    if (lane == 0) smem[wid] = acc;
    __syncthreads();
    if (threadIdx.x == 0) {
        float s = 0.0f;
        #pragma unroll
        for (int i = 0; i < WPB; ++i) s += smem[i];
        g_partials[blockIdx.x] = s;
    }
}

__global__ void __launch_bounds__(512) sg_final_reduce(float* out, int nblocks)
{
    const int lane = threadIdx.x & 31;
    const int wid  = threadIdx.x >> 5;
    float v = 0.0f;
    for (int i = threadIdx.x; i < nblocks; i += blockDim.x)
        v += g_partials[i];
    #pragma unroll
    for (int o = 16; o > 0; o >>= 1)
        v += __shfl_xor_sync(0xffffffffu, v, o);
    __shared__ float smem[16];
    if (lane == 0) smem[wid] = v;
    __syncthreads();
    if (threadIdx.x == 0) {
        float s = 0.0f;
        #pragma unroll
        for (int i = 0; i < 16; ++i) s += smem[i];
        out[0] = s;
    }
}

extern "C" void kernel_launch(void* const* d_in, const int* in_sizes, int n_in,
                              void* d_out, int out_size)
{
    const float* W0      = (const float*)d_in[0];
    const float* W1      = (const float*)d_in[1];
    const int*   target  = (const int*)d_in[2];
    const int*   context = (const int*)d_in[3];
    const int*   codes   = (const int*)d_in[4];
    const int*   lengths = (const int*)d_in[5];
    float* out = (float*)d_out;

    const int B = in_sizes[2];                  // 16384
    const int n_nodes = in_sizes[0] / DIM;      // 1,000,000
    const int elems_per_cta = WPB * EPW;        // 32
    int blocks = (B + elems_per_cta - 1) / elems_per_cta;   // 512
    if (blocks > 2048) blocks = 2048;           // scratch bound (B<=65536 here)

    sg_loss_kernel<<<blocks, 256>>>(W0, W1, target, context, codes, lengths, B, n_nodes);
    sg_final_reduce<<<1, 512>>>(out, blocks);
}

// round 5
// speedup vs baseline: 1.0239x; 1.0239x over previous
#include <cuda_runtime.h>

#define DIM   128
#define LMAX  20
#define EPW   4      // elements per warp
#define WPB   8      // warps per block  -> 32 elements per CTA

__device__ float g_partials[2048];
__device__ unsigned int g_counter = 0;

__global__ void __launch_bounds__(256) sg_loss_kernel(
    const float* __restrict__ W0,
    const float* __restrict__ W1,
    const int* __restrict__ target,
    const int* __restrict__ context,
    const int* __restrict__ codes,
    const int* __restrict__ lengths,
    float* __restrict__ out,
    int B, int n_nodes)
{
    const int lane  = threadIdx.x & 31;
    const int wid   = threadIdx.x >> 5;
    const int gwarp = blockIdx.x * WPB + wid;
    const int base  = gwarp * EPW;

    float acc = 0.0f;   // per-lane accumulator over all 4 elements

    if (base < B) {
        // ---- phase 1: issue ALL independent small loads up front ----
        int t[EPW], c[EPW], len[EPW], code[EPW];
        #pragma unroll
        for (int e = 0; e < EPW; ++e) {
            const int i = base + e;
            t[e]    = (i < B) ? target[i]  : 0;   // broadcast loads
            c[e]    = (i < B) ? context[i] : 0;
            len[e]  = (i < B) ? lengths[i] : 0;
            code[e] = (i < B && lane < LMAX) ? codes[i * LMAX + lane] : 0;
        }

        // ---- phase 2: 8 row gathers back-to-back (MLP=8) ----
        float4 a[EPW], b[EPW];
        #pragma unroll
        for (int e = 0; e < EPW; ++e) {
            const bool ok = (base + e < B) &&
                            t[e] >= 0 && t[e] < n_nodes &&
                            c[e] >= 0 && c[e] < n_nodes;
            const long long ti = ok ? (long long)t[e] : 0;
            const long long ci = ok ? (long long)c[e] : 0;
            a[e] = reinterpret_cast<const float4*>(W0 + ti * DIM)[lane];
            b[e] = reinterpret_cast<const float4*>(W1 + ci * DIM)[lane];
            if (!ok) len[e] = 0;   // contributes nothing
        }

        // ---- phase 3: compute ----
        #pragma unroll
        for (int e = 0; e < EPW; ++e) {
            float dot = a[e].x * b[e].x + a[e].y * b[e].y
                      + a[e].z * b[e].z + a[e].w * b[e].w;
            #pragma unroll
            for (int o = 16; o > 0; o >>= 1)
                dot += __shfl_xor_sync(0xffffffffu, dot, o);
            // all lanes hold full dot; lanes 0..len-1 evaluate tree levels
            if (lane < len[e]) {
                const float sign = 1.0f - 2.0f * (float)code[e];
                const float x = sign * dot;
                // stable log_sigmoid: min(x,0) - log1p(exp(-|x|))
                acc -= fminf(x, 0.0f) - log1pf(__expf(-fabsf(x)));
            }
        }
    }

    // ---- warp + block reduce (no atomics) ----
    #pragma unroll
    for (int o = 16; o > 0; o >>= 1)
        acc += __shfl_xor_sync(0xffffffffu, acc, o);

    __shared__ float smem[WPB];
    __shared__ bool  is_last;
    if (lane == 0) smem[wid] = acc;
    __syncthreads();
    if (threadIdx.x == 0) {
        float s = 0.0f;
        #pragma unroll
        for (int i = 0; i < WPB; ++i) s += smem[i];
        g_partials[blockIdx.x] = s;
        __threadfence();
        const unsigned int old = atomicAdd(&g_counter, 1u);
        is_last = (old == gridDim.x - 1);
    }
    __syncthreads();

    // ---- last CTA: final reduce of all partials (deterministic order) ----
    if (is_last) {
        __threadfence();
        const int nb = gridDim.x;
        float v = 0.0f;
        for (int i = threadIdx.x; i < nb; i += blockDim.x)
            v += g_partials[i];
        #pragma unroll
        for (int o = 16; o > 0; o >>= 1)
            v += __shfl_xor_sync(0xffffffffu, v, o);
        __shared__ float smem2[WPB];
        if (lane == 0) smem2[wid] = v;
        __syncthreads();
        if (threadIdx.x == 0) {
            float s = 0.0f;
            #pragma unroll
            for (int i = 0; i < WPB; ++i) s += smem2[i];
            out[0] = s;
            g_counter = 0;   // reset for next graph replay
        }
    }
}

extern "C" void kernel_launch(void* const* d_in, const int* in_sizes, int n_in,
                              void* d_out, int out_size)
{
    const float* W0      = (const float*)d_in[0];
    const float* W1      = (const float*)d_in[1];
    const int*   target  = (const int*)d_in[2];
    const int*   context = (const int*)d_in[3];
    const int*   codes   = (const int*)d_in[4];
    const int*   lengths = (const int*)d_in[5];
    float* out = (float*)d_out;

    const int B = in_sizes[2];                  // 16384
    const int n_nodes = in_sizes[0] / DIM;      // 1,000,000
    const int elems_per_cta = WPB * EPW;        // 32
    int blocks = (B + elems_per_cta - 1) / elems_per_cta;   // 512
    if (blocks > 2048) blocks = 2048;           // scratch bound

    sg_loss_kernel<<<blocks, 256>>>(W0, W1, target, context, codes, lengths, out, B, n_nodes);
}